// round 9
// baseline (speedup 1.0000x reference)
#include <cuda_runtime.h>
#include <cstdint>

#define B_ 2
#define H_ 8
#define S_ 1024
#define DK_ 64
#define DV_ 64
static constexpr float INV_T = 0.125f;                   // 1/temperature
static constexpr int OUT_ATTN_OFF = B_ * H_ * S_ * DV_;  // 1048576

// ---- packed fp32 helpers (sm_103a f32x2 pipe) -------------------------------
#define FMA2(acc, a, b) asm("fma.rn.f32x2 %0, %1, %2, %0;" : "+l"(acc) : "l"(a), "l"(b))

__device__ __forceinline__ unsigned long long pack2(float lo, float hi) {
    unsigned long long r;
    asm("mov.b64 %0, {%1, %2};" : "=l"(r) : "f"(lo), "f"(hi));
    return r;
}
__device__ __forceinline__ float2 unpack2(unsigned long long v) {
    float2 r;
    asm("mov.b64 {%0, %1}, %2;" : "=f"(r.x), "=f"(r.y) : "l"(v));
    return r;
}

// ---- cp.async helpers -------------------------------------------------------
__device__ __forceinline__ uint32_t s2u(const void* p) {
    return (uint32_t)__cvta_generic_to_shared(p);
}
__device__ __forceinline__ void cp8(uint32_t dst, const void* src) {
    asm volatile("cp.async.ca.shared.global [%0], [%1], 8;" :: "r"(dst), "l"(src));
}
__device__ __forceinline__ void cp16(uint32_t dst, const void* src) {
    asm volatile("cp.async.cg.shared.global [%0], [%1], 16;" :: "r"(dst), "l"(src));
}
#define CP_COMMIT() asm volatile("cp.async.commit_group;")
#define CP_WAIT1()  asm volatile("cp.async.wait_group 1;")
#define CP_WAIT0()  asm volatile("cp.async.wait_group 0;")

// ---------------------------------------------------------------------------
// K1 (R7, measured 49.7us): attn1 = (q/T).k^T, d-parity packing, no transpose.
// Tile 128i x 64j, 256 threads, 8x4 micro (j strided by 16).
// ---------------------------------------------------------------------------
static constexpr int K1_PITCH = 66;
static constexpr int K1_SMEM = (128 + 64) * K1_PITCH * 4;   // 50688 B

__global__ void __launch_bounds__(256, 2) k1_qk(const float* __restrict__ q,
                                                const float* __restrict__ k,
                                                float* __restrict__ attn)
{
    extern __shared__ float sm1[];
    float* Qs = sm1;                    // [128][66]
    float* Ks = sm1 + 128 * K1_PITCH;   // [64][66]

    const int bh = blockIdx.z;
    const int i0 = blockIdx.y * 128;
    const int j0 = blockIdx.x * 64;
    const float* qb = q + ((size_t)bh * S_ + i0) * DK_;
    const float* kb = k + ((size_t)bh * S_ + j0) * DK_;
    const int t = threadIdx.x;
    const uint32_t qs_u = s2u(Qs), ks_u = s2u(Ks);

    #pragma unroll
    for (int m = 0; m < 16; m++) {
        const int idx = m * 256 + t;
        const int row = idx >> 5, p = idx & 31;
        cp8(qs_u + (uint32_t)(row * K1_PITCH + 2 * p) * 4u, qb + (size_t)idx * 2);
    }
    #pragma unroll
    for (int m = 0; m < 8; m++) {
        const int idx = m * 256 + t;
        const int row = idx >> 5, p = idx & 31;
        cp8(ks_u + (uint32_t)(row * K1_PITCH + 2 * p) * 4u, kb + (size_t)idx * 2);
    }
    CP_COMMIT();
    CP_WAIT0();
    __syncthreads();

    const int tx = t & 15;
    const int ty = t >> 4;
    const float* qp = Qs + (ty * 8) * K1_PITCH;
    const float* kp = Ks + tx * K1_PITCH;

    unsigned long long acc[8][4] = {};

    #pragma unroll 8
    for (int dp = 0; dp < 32; dp++) {
        unsigned long long kv[4], qv[8];
        #pragma unroll
        for (int s = 0; s < 4; s++)
            kv[s] = *(const unsigned long long*)(kp + (16 * s) * K1_PITCH + 2 * dp);
        #pragma unroll
        for (int r = 0; r < 8; r++)
            qv[r] = *(const unsigned long long*)(qp + r * K1_PITCH + 2 * dp);
        #pragma unroll
        for (int r = 0; r < 8; r++)
            #pragma unroll
            for (int s = 0; s < 4; s++)
                FMA2(acc[r][s], qv[r], kv[s]);
    }

    #pragma unroll
    for (int r = 0; r < 8; r++) {
        float* row = attn + (((size_t)bh * S_ + i0 + ty * 8 + r) * S_) + j0;
        #pragma unroll
        for (int s = 0; s < 4; s++) {
            float2 pv = unpack2(acc[r][s]);
            row[tx + 16 * s] = (pv.x + pv.y) * INV_T;
        }
    }
}

// ---------------------------------------------------------------------------
// K2 (R6 frame + d-parity inner loop, split per batch):
// per (b,i): logits[h][j] = attn1[h][j] + qs[h,:].rpr[b,i,j,:]; mask; softmax.
// Thread t owns j=c*256+t for all 8 heads; logits in registers; chunk 256,
// 2-deep cp16 pipeline; qs pre-packed [dp][h][e] -> zero dup2.
// Launched once per batch b (grid 1024) so the profiler slot rotates.
// ---------------------------------------------------------------------------
static constexpr int K2_CHUNK = 256;
static constexpr int K2_PITCH = 68;                        // 16B rows, xbar-clean
static constexpr int K2_BUF = K2_CHUNK * K2_PITCH;         // 17408 floats
static constexpr int K2_SMEM_TOTAL = (512 + 128 + 2 * K2_BUF) * 4;  // 141824 B

__device__ __forceinline__ void k2_stage(uint32_t rs_u, const float* __restrict__ src,
                                         int t)
{
    #pragma unroll
    for (int m = 0; m < 16; m++) {
        const int idx = m * 256 + t;
        const int j = idx >> 4;
        const int g = idx & 15;
        cp16(rs_u + (uint32_t)(j * K2_PITCH + g * 4) * 4u, src + (size_t)idx * 4);
    }
    CP_COMMIT();
}

__global__ void __launch_bounds__(256, 1) k2_rpr_softmax(
    const float* __restrict__ q,
    const float* __restrict__ rpr,
    const int* __restrict__ mask,
    float* __restrict__ attn,
    int b)
{
    extern __shared__ float sm2[];
    float* qs3  = sm2;            // [32 dp][8 h][2 e] = 512
    float* redm = sm2 + 512;      // [8][8] partial reductions
    float* fval = sm2 + 576;      // [8] per-head max / inv-sum (uses redm tail)
    float* rs0  = sm2 + 640;      // [256][68]
    float* rs1  = rs0 + K2_BUF;

    const int i = blockIdx.x;
    const int t = threadIdx.x;
    const int w = t >> 5, lane = t & 31;

    const float* rbase = rpr + ((size_t)b * S_ + i) * S_ * DK_;
    const int* mrow = mask + ((size_t)b * S_ + i) * S_;
    const uint32_t ru[2] = { s2u(rs0), s2u(rs1) };
    const float* rp[2] = { rs0, rs1 };

    k2_stage(ru[0], rbase, t);          // chunk 0 in flight first

    // qs3[dp][h][e] = q[b,h,i,2dp+e]/T   (overlaps first stage)
    #pragma unroll
    for (int idx = t; idx < 512; idx += 256) {
        const int e = idx & 1, h = (idx >> 1) & 7, dp = idx >> 4;
        qs3[idx] = q[(((size_t)b * H_ + h) * S_ + i) * DK_ + 2 * dp + e] * INV_T;
    }

    float l[8][4];                      // logits: [head][chunk], j = c*256+t

    #pragma unroll
    for (int c = 0; c < 4; c++) {
        if (c) __syncthreads();         // readers of buf[(c+1)&1] (iter c-1) done

        const int j = c * K2_CHUNK + t;
        const int mk = mrow[j];
        float a1v[8];                   // attn1 prefetch (L2-hot, overlaps cp)
        #pragma unroll
        for (int h = 0; h < 8; h++)
            a1v[h] = attn[(((size_t)b * H_ + h) * S_ + i) * S_ + j];

        if (c < 3) {
            k2_stage(ru[(c + 1) & 1], rbase + (size_t)(c + 1) * K2_CHUNK * DK_, t);
            CP_WAIT1();
        } else {
            CP_WAIT0();
        }
        __syncthreads();

        unsigned long long acc[8] = {};          // per head, (even-d, odd-d)
        const float* rr = rp[c & 1] + t * K2_PITCH;
        #pragma unroll
        for (int g = 0; g < 16; g++) {
            ulonglong2 rpv = *(const ulonglong2*)(rr + 4 * g);  // dp=2g, 2g+1
            const float* q0 = qs3 + (2 * g) * 16;               // dp=2g row
            ulonglong2 qA = *(const ulonglong2*)(q0);           // h0,h1
            ulonglong2 qB = *(const ulonglong2*)(q0 + 4);       // h2,h3
            ulonglong2 qC = *(const ulonglong2*)(q0 + 8);       // h4,h5
            ulonglong2 qD = *(const ulonglong2*)(q0 + 12);      // h6,h7
            FMA2(acc[0], qA.x, rpv.x); FMA2(acc[1], qA.y, rpv.x);
            FMA2(acc[2], qB.x, rpv.x); FMA2(acc[3], qB.y, rpv.x);
            FMA2(acc[4], qC.x, rpv.x); FMA2(acc[5], qC.y, rpv.x);
            FMA2(acc[6], qD.x, rpv.x); FMA2(acc[7], qD.y, rpv.x);
            const float* q1 = q0 + 16;                          // dp=2g+1 row
            ulonglong2 qE = *(const ulonglong2*)(q1);
            ulonglong2 qF = *(const ulonglong2*)(q1 + 4);
            ulonglong2 qG = *(const ulonglong2*)(q1 + 8);
            ulonglong2 qH = *(const ulonglong2*)(q1 + 12);
            FMA2(acc[0], qE.x, rpv.y); FMA2(acc[1], qE.y, rpv.y);
            FMA2(acc[2], qF.x, rpv.y); FMA2(acc[3], qF.y, rpv.y);
            FMA2(acc[4], qG.x, rpv.y); FMA2(acc[5], qG.y, rpv.y);
            FMA2(acc[6], qH.x, rpv.y); FMA2(acc[7], qH.y, rpv.y);
        }

        #pragma unroll
        for (int h = 0; h < 8; h++) {
            float2 pv = unpack2(acc[h]);
            l[h][c] = mk ? (pv.x + pv.y + a1v[h]) : -1e9f;
        }
    }

    // ---- block softmax (R6 code) ----
    #pragma unroll
    for (int h = 0; h < 8; h++) {
        float m = fmaxf(fmaxf(l[h][0], l[h][1]), fmaxf(l[h][2], l[h][3]));
        #pragma unroll
        for (int o = 16; o > 0; o >>= 1)
            m = fmaxf(m, __shfl_xor_sync(0xffffffffu, m, o));
        if (lane == 0) redm[h * 8 + w] = m;
    }
    __syncthreads();
    {
        float m2 = redm[w * 8 + (lane & 7)];
        #pragma unroll
        for (int o = 4; o > 0; o >>= 1)
            m2 = fmaxf(m2, __shfl_xor_sync(0xffffffffu, m2, o, 8));
        if (lane == 0) fval[w] = m2;
    }
    __syncthreads();
    float mxs[8];
    #pragma unroll
    for (int h = 0; h < 8; h++) mxs[h] = fval[h];
    __syncthreads();

    #pragma unroll
    for (int h = 0; h < 8; h++) {
        float s = 0.f;
        #pragma unroll
        for (int c = 0; c < 4; c++) {
            l[h][c] = __expf(l[h][c] - mxs[h]);
            s += l[h][c];
        }
        #pragma unroll
        for (int o = 16; o > 0; o >>= 1)
            s += __shfl_xor_sync(0xffffffffu, s, o);
        if (lane == 0) redm[h * 8 + w] = s;
    }
    __syncthreads();
    {
        float s2 = redm[w * 8 + (lane & 7)];
        #pragma unroll
        for (int o = 4; o > 0; o >>= 1)
            s2 += __shfl_xor_sync(0xffffffffu, s2, o, 8);
        if (lane == 0) fval[w] = 1.0f / s2;
    }
    __syncthreads();

    #pragma unroll
    for (int h = 0; h < 8; h++) {
        const float rinv = fval[h];
        float* arow = attn + (((size_t)b * H_ + h) * S_ + i) * S_;
        #pragma unroll
        for (int c = 0; c < 4; c++)
            arow[c * K2_CHUNK + t] = l[h][c] * rinv;
    }
}

// ---------------------------------------------------------------------------
// K3 (R7): output = attn @ v, j-parity packing, 32-row tiles, grid 512,
// double-buffered cp16.
// ---------------------------------------------------------------------------
static constexpr int K3_AS = 32 * 64;                    // 2048 floats
static constexpr int K3_VS = 64 * 64;                    // 4096 floats
static constexpr int K3_SMEM = 2 * (K3_AS + K3_VS) * 4;  // 49152 B

__device__ __forceinline__ void k3_stage(uint32_t as_u, uint32_t vs_u,
                                         const float* __restrict__ ab,
                                         const float* __restrict__ vb,
                                         int jc, int t)
{
    #pragma unroll
    for (int m = 0; m < 2; m++) {
        const int idx = m * 256 + t;
        const int row = idx >> 4;
        const int d4  = (idx & 15) << 2;
        cp16(as_u + (uint32_t)(row * 64 + d4) * 4u, ab + (size_t)row * S_ + jc + d4);
    }
    #pragma unroll
    for (int m = 0; m < 4; m++) {
        const int idx = m * 256 + t;
        const int row = idx >> 4;
        const int d4  = (idx & 15) << 2;
        cp16(vs_u + (uint32_t)(row * 64 + d4) * 4u, vb + (size_t)(jc + row) * DV_ + d4);
    }
    CP_COMMIT();
}

__global__ void __launch_bounds__(256, 4) k3_av(const float* __restrict__ attn,
                                                const float* __restrict__ v,
                                                float* __restrict__ out)
{
    extern __shared__ float sm3[];
    float* Asb[2] = { sm3,                    sm3 + (K3_AS + K3_VS) };
    float* Vsb[2] = { sm3 + K3_AS,            sm3 + (K3_AS + K3_VS) + K3_AS };

    const int bh = blockIdx.y;
    const int i0 = blockIdx.x * 32;
    const int t = threadIdx.x;
    const int iblk = t >> 6;
    const int n = t & 63;
    const float* ab = attn + ((size_t)bh * S_ + i0) * S_;
    const float* vb = v + (size_t)bh * S_ * DV_;
    const uint32_t as_u[2] = { s2u(Asb[0]), s2u(Asb[1]) };
    const uint32_t vs_u[2] = { s2u(Vsb[0]), s2u(Vsb[1]) };

    unsigned long long acc[8] = {};

    k3_stage(as_u[0], vs_u[0], ab, vb, 0, t);

    for (int c = 0; c < 16; c++) {
        if (c < 15) {
            k3_stage(as_u[(c + 1) & 1], vs_u[(c + 1) & 1], ab, vb, (c + 1) * 64, t);
            CP_WAIT1();
        } else {
            CP_WAIT0();
        }
        __syncthreads();

        const float* As = Asb[c & 1] + iblk * 8 * 64;
        const float* Vs = Vsb[c & 1];
        #pragma unroll 4
        for (int jp2 = 0; jp2 < 16; jp2++) {
            const float* vc = Vs + (4 * jp2) * 64 + n;
            unsigned long long vp0 = pack2(vc[0],   vc[64]);
            unsigned long long vp1 = pack2(vc[128], vc[192]);
            #pragma unroll
            for (int r = 0; r < 8; r++) {
                ulonglong2 ap = *(const ulonglong2*)(As + r * 64 + 4 * jp2);
                FMA2(acc[r], ap.x, vp0);
                FMA2(acc[r], ap.y, vp1);
            }
        }
        __syncthreads();
    }

    float* ob = out + ((size_t)bh * S_ + i0 + iblk * 8) * DV_ + n;
    #pragma unroll
    for (int r = 0; r < 8; r++) {
        float2 pv = unpack2(acc[r]);
        ob[(size_t)r * DV_] = pv.x + pv.y;
    }
}

// ---------------------------------------------------------------------------
extern "C" void kernel_launch(void* const* d_in, const int* in_sizes, int n_in,
                              void* d_out, int out_size)
{
    const float* q    = (const float*)d_in[0];
    const float* k    = (const float*)d_in[1];
    const float* v    = (const float*)d_in[2];
    const int*   mask = (const int*)d_in[3];
    const float* rpr  = (const float*)d_in[4];
    float* out  = (float*)d_out;
    float* attn = out + OUT_ATTN_OFF;

    cudaFuncSetAttribute(k1_qk, cudaFuncAttributeMaxDynamicSharedMemorySize, K1_SMEM);
    cudaFuncSetAttribute(k2_rpr_softmax, cudaFuncAttributeMaxDynamicSharedMemorySize,
                         K2_SMEM_TOTAL);
    cudaFuncSetAttribute(k3_av, cudaFuncAttributeMaxDynamicSharedMemorySize, K3_SMEM);

    {   // K1: attn1 logits into attn region (scratch, rewritten by K2)
        dim3 grid(S_ / 64, S_ / 128, B_ * H_);
        k1_qk<<<grid, 256, K1_SMEM>>>(q, k, attn);
    }
    {   // K2: + positional term, mask, softmax — one launch per batch
        dim3 grid(S_, 1);
        k2_rpr_softmax<<<grid, 256, K2_SMEM_TOTAL>>>(q, rpr, mask, attn, 0);
        k2_rpr_softmax<<<grid, 256, K2_SMEM_TOTAL>>>(q, rpr, mask, attn, 1);
    }
    {   // K3: output = attn @ v
        dim3 grid(S_ / 32, B_ * H_);
        k3_av<<<grid, 256, K3_SMEM>>>(attn, v, out);
    }
}

// round 10
// speedup vs baseline: 1.3491x; 1.3491x over previous
#include <cuda_runtime.h>
#include <cstdint>

#define B_ 2
#define H_ 8
#define S_ 1024
#define DK_ 64
#define DV_ 64
static constexpr float INV_T = 0.125f;                   // 1/temperature
static constexpr int OUT_ATTN_OFF = B_ * H_ * S_ * DV_;  // 1048576

// ---- packed fp32 helpers (sm_103a f32x2 pipe) -------------------------------
#define FMA2(acc, a, b) asm("fma.rn.f32x2 %0, %1, %2, %0;" : "+l"(acc) : "l"(a), "l"(b))

__device__ __forceinline__ float2 unpack2(unsigned long long v) {
    float2 r;
    asm("mov.b64 {%0, %1}, %2;" : "=f"(r.x), "=f"(r.y) : "l"(v));
    return r;
}

// ---- cp.async helpers -------------------------------------------------------
__device__ __forceinline__ uint32_t s2u(const void* p) {
    return (uint32_t)__cvta_generic_to_shared(p);
}
__device__ __forceinline__ void cp8(uint32_t dst, const void* src) {
    asm volatile("cp.async.ca.shared.global [%0], [%1], 8;" :: "r"(dst), "l"(src));
}
__device__ __forceinline__ void cp16(uint32_t dst, const void* src) {
    asm volatile("cp.async.cg.shared.global [%0], [%1], 16;" :: "r"(dst), "l"(src));
}
#define CP_COMMIT() asm volatile("cp.async.commit_group;")
#define CP_WAIT1()  asm volatile("cp.async.wait_group 1;")
#define CP_WAIT0()  asm volatile("cp.async.wait_group 0;")

// ---------------------------------------------------------------------------
// K1 (measured 49.7us): attn1 = (q/T).k^T, d-parity packing, no transpose.
// Tile 128i x 64j, 256 threads, 8x4 micro (j strided by 16).
// ---------------------------------------------------------------------------
static constexpr int K1_PITCH = 66;
static constexpr int K1_SMEM = (128 + 64) * K1_PITCH * 4;   // 50688 B

__global__ void __launch_bounds__(256, 2) k1_qk(const float* __restrict__ q,
                                                const float* __restrict__ k,
                                                float* __restrict__ attn)
{
    extern __shared__ float sm1[];
    float* Qs = sm1;                    // [128][66]
    float* Ks = sm1 + 128 * K1_PITCH;   // [64][66]

    const int bh = blockIdx.z;
    const int i0 = blockIdx.y * 128;
    const int j0 = blockIdx.x * 64;
    const float* qb = q + ((size_t)bh * S_ + i0) * DK_;
    const float* kb = k + ((size_t)bh * S_ + j0) * DK_;
    const int t = threadIdx.x;
    const uint32_t qs_u = s2u(Qs), ks_u = s2u(Ks);

    #pragma unroll
    for (int m = 0; m < 16; m++) {
        const int idx = m * 256 + t;
        const int row = idx >> 5, p = idx & 31;
        cp8(qs_u + (uint32_t)(row * K1_PITCH + 2 * p) * 4u, qb + (size_t)idx * 2);
    }
    #pragma unroll
    for (int m = 0; m < 8; m++) {
        const int idx = m * 256 + t;
        const int row = idx >> 5, p = idx & 31;
        cp8(ks_u + (uint32_t)(row * K1_PITCH + 2 * p) * 4u, kb + (size_t)idx * 2);
    }
    CP_COMMIT();
    CP_WAIT0();
    __syncthreads();

    const int tx = t & 15;
    const int ty = t >> 4;
    const float* qp = Qs + (ty * 8) * K1_PITCH;
    const float* kp = Ks + tx * K1_PITCH;

    unsigned long long acc[8][4] = {};

    #pragma unroll 8
    for (int dp = 0; dp < 32; dp++) {
        unsigned long long kv[4], qv[8];
        #pragma unroll
        for (int s = 0; s < 4; s++)
            kv[s] = *(const unsigned long long*)(kp + (16 * s) * K1_PITCH + 2 * dp);
        #pragma unroll
        for (int r = 0; r < 8; r++)
            qv[r] = *(const unsigned long long*)(qp + r * K1_PITCH + 2 * dp);
        #pragma unroll
        for (int r = 0; r < 8; r++)
            #pragma unroll
            for (int s = 0; s < 4; s++)
                FMA2(acc[r][s], qv[r], kv[s]);
    }

    #pragma unroll
    for (int r = 0; r < 8; r++) {
        float* row = attn + (((size_t)bh * S_ + i0 + ty * 8 + r) * S_) + j0;
        #pragma unroll
        for (int s = 0; s < 4; s++) {
            float2 pv = unpack2(acc[r][s]);
            row[tx + 16 * s] = (pv.x + pv.y) * INV_T;
        }
    }
}

// ---------------------------------------------------------------------------
// K2 (best measured config, ~136us inferred): head-group split, chunk 128,
// d-parity inner loop, double-buffered cp16, 2 CTAs/SM.
// ---------------------------------------------------------------------------
static constexpr int K2_CHUNK = 128;
static constexpr int K2_PITCH = 68;                      // 16B-aligned rows
static constexpr int K2_BUF = K2_CHUNK * K2_PITCH;       // 8704 floats
static constexpr int K2_SMEM = (576 + 2 * K2_BUF) * 4;   // 71936 B

__device__ __forceinline__ void k2_stage(uint32_t rs_u, const float* __restrict__ src,
                                         int t)
{
    #pragma unroll
    for (int m = 0; m < 8; m++) {
        const int idx = m * 256 + t;
        const int row = idx >> 4;
        const int gg  = idx & 15;
        cp16(rs_u + (uint32_t)(row * K2_PITCH + 4 * gg) * 4u, src + (size_t)idx * 4);
    }
    CP_COMMIT();
}

__global__ void __launch_bounds__(256, 2) k2_rpr_softmax(
    const float* __restrict__ q,
    const float* __restrict__ rpr,
    const int* __restrict__ mask,
    float* __restrict__ attn)
{
    extern __shared__ float sm2[];
    float* qs3   = sm2;             // [32 dp][8 h][2 e] = 512
    float* redmx = sm2 + 512;       // [8 h][4 warps]
    float* redsm = sm2 + 544;       // [8 h][4 warps]
    float* rs0   = sm2 + 576;       // [128][68]
    float* rs1   = rs0 + K2_BUF;

    const int b = blockIdx.y;
    const int i = blockIdx.x;
    const int t = threadIdx.x;
    const int g = t >> 7;           // head group: heads g*4 .. g*4+3
    const int hb = g * 4;
    const int jl = t & 127;
    const int w = t >> 5, lane = t & 31;

    const float* rbase = rpr + ((size_t)b * S_ + i) * S_ * DK_;
    const int* mrow = mask + ((size_t)b * S_ + i) * S_;
    const uint32_t ru[2] = { s2u(rs0), s2u(rs1) };
    const float* rp2[2] = { rs0, rs1 };

    k2_stage(ru[0], rbase, t);      // chunk 0 in flight first

    // qs3[dp][h][e] = q[b,h,i,2dp+e]/T  (overlaps the first stage)
    #pragma unroll
    for (int idx = t; idx < 512; idx += 256) {
        const int e = idx & 1, h = (idx >> 1) & 7, dp = idx >> 4;
        qs3[idx] = q[(((size_t)b * H_ + h) * S_ + i) * DK_ + 2 * dp + e] * INV_T;
    }

    float l[4][8];                  // [head-in-group][chunk]

    #pragma unroll
    for (int c = 0; c < 8; c++) {
        if (c) __syncthreads();     // prior readers of buf[(c+1)&1] done

        const int j = c * K2_CHUNK + jl;
        if (c < 7) {
            k2_stage(ru[(c + 1) & 1], rbase + (size_t)(c + 1) * K2_CHUNK * DK_, t);
        }

        const int mk = mrow[j];
        float a1v[4];               // attn1 prefetch for this thread's 4 heads
        #pragma unroll
        for (int hh = 0; hh < 4; hh++)
            a1v[hh] = attn[(((size_t)b * H_ + hb + hh) * S_ + i) * S_ + j];

        if (c < 7) { CP_WAIT1(); } else { CP_WAIT0(); }
        __syncthreads();

        unsigned long long acc[4] = {};      // per head, packed (even-d, odd-d)
        const float* rr = rp2[c & 1] + jl * K2_PITCH;
        #pragma unroll
        for (int gg = 0; gg < 16; gg++) {
            ulonglong2 rpv = *(const ulonglong2*)(rr + 4 * gg);  // dp=2gg, 2gg+1
            const float* qb0 = qs3 + (2 * gg) * 16 + hb * 2;
            ulonglong2 qA = *(const ulonglong2*)(qb0);           // dp0: h hb,hb+1
            ulonglong2 qB = *(const ulonglong2*)(qb0 + 4);       // dp0: h hb+2,hb+3
            ulonglong2 qC = *(const ulonglong2*)(qb0 + 16);      // dp1
            ulonglong2 qD = *(const ulonglong2*)(qb0 + 20);
            FMA2(acc[0], qA.x, rpv.x);
            FMA2(acc[1], qA.y, rpv.x);
            FMA2(acc[2], qB.x, rpv.x);
            FMA2(acc[3], qB.y, rpv.x);
            FMA2(acc[0], qC.x, rpv.y);
            FMA2(acc[1], qC.y, rpv.y);
            FMA2(acc[2], qD.x, rpv.y);
            FMA2(acc[3], qD.y, rpv.y);
        }
        #pragma unroll
        for (int hh = 0; hh < 4; hh++) {
            float2 pv = unpack2(acc[hh]);
            l[hh][c] = mk ? (pv.x + pv.y + a1v[hh]) : -1e9f;
        }
    }

    // ---- block softmax: head h lives on 4 warps (one head-group half) ----
    #pragma unroll
    for (int hh = 0; hh < 4; hh++) {
        float m = l[hh][0];
        #pragma unroll
        for (int c = 1; c < 8; c++) m = fmaxf(m, l[hh][c]);
        #pragma unroll
        for (int o = 16; o > 0; o >>= 1)
            m = fmaxf(m, __shfl_xor_sync(0xffffffffu, m, o));
        if (lane == 0) redmx[(hb + hh) * 4 + (w & 3)] = m;
    }
    __syncthreads();
    float mx[4];
    #pragma unroll
    for (int hh = 0; hh < 4; hh++) {
        const float* p = redmx + (hb + hh) * 4;
        mx[hh] = fmaxf(fmaxf(p[0], p[1]), fmaxf(p[2], p[3]));
    }
    #pragma unroll
    for (int hh = 0; hh < 4; hh++) {
        float s = 0.f;
        #pragma unroll
        for (int c = 0; c < 8; c++) {
            l[hh][c] = __expf(l[hh][c] - mx[hh]);
            s += l[hh][c];
        }
        #pragma unroll
        for (int o = 16; o > 0; o >>= 1)
            s += __shfl_xor_sync(0xffffffffu, s, o);
        if (lane == 0) redsm[(hb + hh) * 4 + (w & 3)] = s;
    }
    __syncthreads();
    #pragma unroll
    for (int hh = 0; hh < 4; hh++) {
        const float* p = redsm + (hb + hh) * 4;
        const float rinv = 1.0f / (p[0] + p[1] + p[2] + p[3]);
        float* arow = attn + (((size_t)b * H_ + hb + hh) * S_ + i) * S_;
        #pragma unroll
        for (int c = 0; c < 8; c++)
            arow[c * K2_CHUNK + jl] = l[hh][c] * rinv;
    }
}

// ---------------------------------------------------------------------------
// K3 (REBUILT as K1-clone): output[b,h,i,:] = sum_j attn[b,h,i,j] * v[b,h,j,:]
// j-parity packing with V staged TRANSPOSED (Vt[n][j], pitch 66) so both FMA2
// operands are natural adjacent LDS.64 pairs — zero dup2/pack in the loop.
// Tile 128i x 64n, 256 threads, 8x4 micro (n strided by 16), j chunks of 64,
// double-buffered: As via coalesced cp8, V via LDG.128 prefetch + STS.
// ---------------------------------------------------------------------------
static constexpr int K3_PITCH = 66;
static constexpr int K3_AS = 128 * K3_PITCH;                 // 8448 floats
static constexpr int K3_VT = 64 * K3_PITCH;                  // 4224 floats
static constexpr int K3_SMEM = 2 * (K3_AS + K3_VT) * 4;      // 101376 B

__device__ __forceinline__ void k3_stage_as(uint32_t as_u, const float* __restrict__ ab,
                                            int jc, int t)
{
    // As[row][0..63] <- attn[i0+row][jc..jc+63]; 4096 cp8, 16/thread, coalesced
    #pragma unroll
    for (int m = 0; m < 16; m++) {
        const int idx = m * 256 + t;
        const int row = idx >> 5, p = idx & 31;
        cp8(as_u + (uint32_t)(row * K3_PITCH + 2 * p) * 4u,
            ab + (size_t)row * S_ + jc + 2 * p);
    }
    CP_COMMIT();
}

__global__ void __launch_bounds__(256, 1) k3_av(const float* __restrict__ attn,
                                                const float* __restrict__ v,
                                                float* __restrict__ out)
{
    extern __shared__ float sm3[];
    float* Asb[2] = { sm3,                     sm3 + (K3_AS + K3_VT) };
    float* Vtb[2] = { sm3 + K3_AS,             sm3 + (K3_AS + K3_VT) + K3_AS };

    const int bh = blockIdx.y;
    const int i0 = blockIdx.x * 128;
    const int t = threadIdx.x;
    const int tx = t & 15;
    const int ty = t >> 4;
    const float* ab = attn + ((size_t)bh * S_ + i0) * S_;
    const float* vb = v + (size_t)bh * S_ * DV_;
    const uint32_t as_u[2] = { s2u(Asb[0]), s2u(Asb[1]) };

    // v LDG mapping (coalesced): idx = m*256+t -> vrow = idx>>4, vc = idx&15
    const int vrow = ((0 * 256 + t) >> 4);   // recomputed per m below

    unsigned long long acc[8][4] = {};   // [i-row r][n-slot s], packed (ej, oj)

    // prologue: prefetch v chunk 0 into regs, As chunk 0 in flight
    float4 vreg[4];
    #pragma unroll
    for (int m = 0; m < 4; m++) {
        const int idx = m * 256 + t;
        vreg[m] = *(const float4*)(vb + (size_t)(idx >> 4) * DV_ + (idx & 15) * 4);
    }
    k3_stage_as(as_u[0], ab, 0, t);

    for (int c = 0; c < 16; c++) {
        const int cur = c & 1;
        CP_WAIT0();                      // As(c) resident (only group in flight)

        // transpose-store v chunk c: Vt[n][j]
        float* Vt = Vtb[cur];
        #pragma unroll
        for (int m = 0; m < 4; m++) {
            const int idx = m * 256 + t;
            const int vr = idx >> 4;      // j within chunk
            const int vc = idx & 15;      // n group
            Vt[(4 * vc + 0) * K3_PITCH + vr] = vreg[m].x;
            Vt[(4 * vc + 1) * K3_PITCH + vr] = vreg[m].y;
            Vt[(4 * vc + 2) * K3_PITCH + vr] = vreg[m].z;
            Vt[(4 * vc + 3) * K3_PITCH + vr] = vreg[m].w;
        }
        __syncthreads();                 // As(c) + Vt(c) visible to all

        if (c < 15) {                    // next chunk in flight during compute
            #pragma unroll
            for (int m = 0; m < 4; m++) {
                const int idx = m * 256 + t;
                vreg[m] = *(const float4*)(vb + (size_t)((c + 1) * 64 + (idx >> 4)) * DV_
                                           + (idx & 15) * 4);
            }
            k3_stage_as(as_u[cur ^ 1], ab, (c + 1) * 64, t);
        }

        const float* ap = Asb[cur] + (ty * 8) * K3_PITCH;
        const float* vp = Vt + tx * K3_PITCH;
        #pragma unroll 8
        for (int jp = 0; jp < 32; jp++) {
            unsigned long long vv[4], av[8];
            #pragma unroll
            for (int s = 0; s < 4; s++)
                vv[s] = *(const unsigned long long*)(vp + (16 * s) * K3_PITCH + 2 * jp);
            #pragma unroll
            for (int r = 0; r < 8; r++)
                av[r] = *(const unsigned long long*)(ap + r * K3_PITCH + 2 * jp);
            #pragma unroll
            for (int r = 0; r < 8; r++)
                #pragma unroll
                for (int s = 0; s < 4; s++)
                    FMA2(acc[r][s], av[r], vv[s]);
        }
        __syncthreads();                 // buf consumed before restage at c+2
    }

    #pragma unroll
    for (int r = 0; r < 8; r++) {
        float* orow = out + ((size_t)bh * S_ + i0 + ty * 8 + r) * DV_;
        #pragma unroll
        for (int s = 0; s < 4; s++) {
            float2 pv = unpack2(acc[r][s]);
            orow[tx + 16 * s] = pv.x + pv.y;
        }
    }
}

// ---------------------------------------------------------------------------
extern "C" void kernel_launch(void* const* d_in, const int* in_sizes, int n_in,
                              void* d_out, int out_size)
{
    const float* q    = (const float*)d_in[0];
    const float* k    = (const float*)d_in[1];
    const float* v    = (const float*)d_in[2];
    const int*   mask = (const int*)d_in[3];
    const float* rpr  = (const float*)d_in[4];
    float* out  = (float*)d_out;
    float* attn = out + OUT_ATTN_OFF;

    cudaFuncSetAttribute(k1_qk, cudaFuncAttributeMaxDynamicSharedMemorySize, K1_SMEM);
    cudaFuncSetAttribute(k2_rpr_softmax, cudaFuncAttributeMaxDynamicSharedMemorySize,
                         K2_SMEM);
    cudaFuncSetAttribute(k3_av, cudaFuncAttributeMaxDynamicSharedMemorySize, K3_SMEM);

    {   // K1: attn1 logits into attn region (scratch, rewritten by K2)
        dim3 grid(S_ / 64, S_ / 128, B_ * H_);
        k1_qk<<<grid, 256, K1_SMEM>>>(q, k, attn);
    }
    {   // K2: + positional term, mask, softmax
        dim3 grid(S_, B_);
        k2_rpr_softmax<<<grid, 256, K2_SMEM>>>(q, rpr, mask, attn);
    }
    {   // K3: output = attn @ v
        dim3 grid(S_ / 128, B_ * H_);
        k3_av<<<grid, 256, K3_SMEM>>>(attn, v, out);
    }
}